// round 3
// baseline (speedup 1.0000x reference)
#include <cuda_runtime.h>
#include <math.h>

#define T    2048
#define F    1024
#define NB   64          // total batch
#define HB   32          // half batch
#define KSEL 20

// scratch (no allocs allowed)
__device__ float g_mags[NB * T];
__device__ int   g_idx[NB * KSEL];

// -------- kernel 1: per-(b,t) L2 norm over feature dim --------
// one warp per row; 8 float4 loads per lane, fully coalesced. HBM-bound
// at ~6.9 TB/s — at the roofline.
__global__ void mag_kernel(const float* __restrict__ feat) {
    int warp = (blockIdx.x * blockDim.x + threadIdx.x) >> 5;  // 0 .. 64*2048-1
    int lane = threadIdx.x & 31;
    const float4* row = (const float4*)(feat + (size_t)warp * F);
    float s = 0.f;
#pragma unroll
    for (int i = 0; i < 8; i++) {
        float4 v = row[lane + i * 32];
        s += v.x * v.x + v.y * v.y + v.z * v.z + v.w * v.w;
    }
#pragma unroll
    for (int o = 16; o; o >>= 1) s += __shfl_xor_sync(0xffffffffu, s, o);
    if (lane == 0) g_mags[warp] = sqrtf(s);
}

// -------- kernel 2: top-K + score mean (register-resident, 64 blocks) ----
// blockIdx.x in [0,32): abnormal (batch 32+b), [32,64): normal (batch b-32).
// 20 rounds: 8 reg cmps -> 5-shfl warp argmax -> 3-shfl cross-warp argmax.
// Stable lowest-index tie-break matches jax.lax.top_k.
__global__ void topk_kernel(const float* __restrict__ scores,
                            const float* __restrict__ mask_abn,
                            const float* __restrict__ mask_nor,
                            float* __restrict__ out) {
    __shared__ float wrv[8];
    __shared__ int   wri[8];
    __shared__ int   s_win;
    __shared__ float s_sc[KSEL];

    int b = blockIdx.x;
    int tid = threadIdx.x;
    int lane = tid & 31;
    int wid = tid >> 5;

    int batch;
    const float* mask;
    if (b < HB) { batch = HB + b; mask = mask_abn + (size_t)b * T; }
    else        { batch = b - HB; mask = mask_nor + (size_t)(b - HB) * T; }

    const float inv = 1.0f / 0.9f;   // 1/(1-P)
    float v[8];
#pragma unroll
    for (int j = 0; j < 8; j++) {
        int t = tid + j * 256;
        float d = (mask[t] > 0.1f) ? inv : 0.0f;
        v[j] = g_mags[batch * T + t] * d;
    }

    for (int k = 0; k < KSEL; k++) {
        // local argmax over 8 regs (ascending index + strict '>' => lowest idx)
        float bv = -1.0f; int bi = 1 << 30;
#pragma unroll
        for (int j = 0; j < 8; j++) {
            if (v[j] > bv) { bv = v[j]; bi = tid + j * 256; }
        }
        // warp argmax, smaller index wins ties
#pragma unroll
        for (int o = 16; o; o >>= 1) {
            float ov = __shfl_xor_sync(0xffffffffu, bv, o);
            int   oi = __shfl_xor_sync(0xffffffffu, bi, o);
            if (ov > bv || (ov == bv && oi < bi)) { bv = ov; bi = oi; }
        }
        if (lane == 0) { wrv[wid] = bv; wri[wid] = bi; }
        __syncthreads();
        if (wid == 0) {
            float fv = (lane < 8) ? wrv[lane] : -2.0f;
            int   fi = (lane < 8) ? wri[lane] : (1 << 30);
#pragma unroll
            for (int o = 4; o; o >>= 1) {
                float ov = __shfl_xor_sync(0xffffffffu, fv, o);
                int   oi = __shfl_xor_sync(0xffffffffu, fi, o);
                if (ov > fv || (ov == fv && oi < fi)) { fv = ov; fi = oi; }
            }
            if (lane == 0) {
                g_idx[b * KSEL + k] = fi;
                s_win = fi;
                s_sc[k] = scores[(size_t)batch * T + fi];
            }
        }
        __syncthreads();
        int w = s_win;
        if ((w & 255) == tid) v[w >> 8] = -1.0f;   // remove winner (vals >= 0)
    }

    if (tid == 0) {
        float s = 0.f;
#pragma unroll
        for (int k = 0; k < KSEL; k++) s += s_sc[k];
        out[b] = s / (float)KSEL;    // [0,32)=score_abnormal, [32,64)=score_normal
    }
}

// -------- kernel 3: gather selected feature rows (wide: 1280 blocks) ------
__global__ void gather_kernel(const float* __restrict__ feat,
                              float* __restrict__ out) {
    int blk = blockIdx.x;
    int row = blk / KSEL;           // 0..63 (abn rows first, then nor)
    int k   = blk % KSEL;
    int batch = (row < HB) ? (HB + row) : (row - HB);
    int idx = g_idx[row * KSEL + k];
    const float4* src = (const float4*)(feat + ((size_t)batch * T + idx) * F);
    float4* dst = (float4*)(out + 64 + ((size_t)row * KSEL + k) * F);
    dst[threadIdx.x] = src[threadIdx.x];
}

extern "C" void kernel_launch(void* const* d_in, const int* in_sizes, int n_in,
                              void* d_out, int out_size) {
    const float* feat   = (const float*)d_in[0];
    const float* scores = (const float*)d_in[1];
    const float* mabn   = (const float*)d_in[2];
    const float* mnor   = (const float*)d_in[3];
    float* out = (float*)d_out;

    mag_kernel<<<(NB * T) / 8, 256>>>(feat);
    topk_kernel<<<NB, 256>>>(scores, mabn, mnor, out);
    gather_kernel<<<NB * KSEL, 256>>>(feat, out);
}

// round 4
// speedup vs baseline: 1.0888x; 1.0888x over previous
#include <cuda_runtime.h>
#include <math.h>

#define T    2048
#define F    1024
#define NB   64          // total batch
#define HB   32          // half batch
#define KSEL 20

// scratch (no allocs allowed)
__device__ float g_mags[NB * T];
__device__ int   g_idx[NB * KSEL];

// -------- kernel 1: per-(b,t) L2 norm over feature dim --------
// one warp per row; 8 float4 loads per lane, fully coalesced. HBM-bound
// at ~6.9 TB/s (86% of spec) — at the measured roofline.
__global__ void mag_kernel(const float* __restrict__ feat) {
    int warp = (blockIdx.x * blockDim.x + threadIdx.x) >> 5;  // 0 .. 64*2048-1
    int lane = threadIdx.x & 31;
    const float4* row = (const float4*)(feat + (size_t)warp * F);
    float s = 0.f;
#pragma unroll
    for (int i = 0; i < 8; i++) {
        float4 v = row[lane + i * 32];
        s += v.x * v.x + v.y * v.y + v.z * v.z + v.w * v.w;
    }
#pragma unroll
    for (int o = 16; o; o >>= 1) s += __shfl_xor_sync(0xffffffffu, s, o);
    if (lane == 0) g_mags[warp] = sqrtf(s);
}

// -------- kernel 2: top-K + score mean (register-resident, 64 blocks) ----
// blockIdx.x in [0,32): abnormal (batch 32+b), [32,64): normal (batch b-32).
// 20 rounds of pure reg/shfl/shared argmax — NO global loads inside the
// loop (that was R3's 10us mistake). Stable lowest-index tie-break matches
// jax.lax.top_k.
__global__ void topk_kernel(const float* __restrict__ scores,
                            const float* __restrict__ mask_abn,
                            const float* __restrict__ mask_nor,
                            float* __restrict__ out) {
    __shared__ float wrv[8];
    __shared__ int   wri[8];
    __shared__ int   s_win;
    __shared__ int   s_idx[KSEL];
    __shared__ float s_sc[KSEL];

    int b = blockIdx.x;
    int tid = threadIdx.x;
    int lane = tid & 31;
    int wid = tid >> 5;

    int batch;
    const float* mask;
    if (b < HB) { batch = HB + b; mask = mask_abn + (size_t)b * T; }
    else        { batch = b - HB; mask = mask_nor + (size_t)(b - HB) * T; }

    const float inv = 1.0f / 0.9f;   // 1/(1-P)
    float v[8];
#pragma unroll
    for (int j = 0; j < 8; j++) {
        int t = tid + j * 256;
        float d = (mask[t] > 0.1f) ? inv : 0.0f;
        v[j] = g_mags[batch * T + t] * d;
    }

    for (int k = 0; k < KSEL; k++) {
        // local argmax over 8 regs (ascending index + strict '>' => lowest idx)
        float bv = -1.0f; int bi = 1 << 30;
#pragma unroll
        for (int j = 0; j < 8; j++) {
            if (v[j] > bv) { bv = v[j]; bi = tid + j * 256; }
        }
        // warp argmax, smaller index wins ties
#pragma unroll
        for (int o = 16; o; o >>= 1) {
            float ov = __shfl_xor_sync(0xffffffffu, bv, o);
            int   oi = __shfl_xor_sync(0xffffffffu, bi, o);
            if (ov > bv || (ov == bv && oi < bi)) { bv = ov; bi = oi; }
        }
        if (lane == 0) { wrv[wid] = bv; wri[wid] = bi; }
        __syncthreads();
        if (wid == 0) {
            float fv = (lane < 8) ? wrv[lane] : -2.0f;
            int   fi = (lane < 8) ? wri[lane] : (1 << 30);
#pragma unroll
            for (int o = 4; o; o >>= 1) {
                float ov = __shfl_xor_sync(0xffffffffu, fv, o);
                int   oi = __shfl_xor_sync(0xffffffffu, fi, o);
                if (ov > fv || (ov == fv && oi < fi)) { fv = ov; fi = oi; }
            }
            if (lane == 0) { s_idx[k] = fi; s_win = fi; }
        }
        __syncthreads();
        int w = s_win;
        if ((w & 255) == tid) v[w >> 8] = -1.0f;   // remove winner (vals >= 0)
    }

    // write indices + mean of selected scores (single parallel load pass)
    if (tid < KSEL) {
        int idx = s_idx[tid];
        g_idx[b * KSEL + tid] = idx;
        s_sc[tid] = scores[(size_t)batch * T + idx];
    }
    __syncthreads();
    if (tid == 0) {
        float s = 0.f;
#pragma unroll
        for (int k = 0; k < KSEL; k++) s += s_sc[k];
        out[b] = s / (float)KSEL;    // [0,32)=score_abnormal, [32,64)=score_normal
    }
}

// -------- kernel 3: gather selected feature rows (wide: 1280 blocks) ------
__global__ void gather_kernel(const float* __restrict__ feat,
                              float* __restrict__ out) {
    int blk = blockIdx.x;
    int row = blk / KSEL;           // 0..63 (abn rows first, then nor)
    int k   = blk % KSEL;
    int batch = (row < HB) ? (HB + row) : (row - HB);
    int idx = g_idx[row * KSEL + k];
    const float4* src = (const float4*)(feat + ((size_t)batch * T + idx) * F);
    float4* dst = (float4*)(out + 64 + ((size_t)row * KSEL + k) * F);
    dst[threadIdx.x] = src[threadIdx.x];
}

extern "C" void kernel_launch(void* const* d_in, const int* in_sizes, int n_in,
                              void* d_out, int out_size) {
    const float* feat   = (const float*)d_in[0];
    const float* scores = (const float*)d_in[1];
    const float* mabn   = (const float*)d_in[2];
    const float* mnor   = (const float*)d_in[3];
    float* out = (float*)d_out;

    mag_kernel<<<(NB * T) / 8, 256>>>(feat);
    topk_kernel<<<NB, 256>>>(scores, mabn, mnor, out);
    gather_kernel<<<NB * KSEL, 256>>>(feat, out);
}